// round 2
// baseline (speedup 1.0000x reference)
#include <cuda_runtime.h>

// Problem constants (fixed shapes)
#define BB 2
#define SS 2048
#define EE 1024
#define HH 16
#define DHD 64

// Scratch (allocation-free: __device__ globals). 4 x 16 MB.
__device__ float g_q[BB * SS * EE];
__device__ float g_k[BB * SS * EE];
__device__ float g_v[BB * SS * EE];
__device__ float g_o[BB * SS * EE];

// ---------------------------------------------------------------------------
// GEMM: C[M,N] = A[M,K] * B[N,K]^T + bias[N]
// Block 128x128, BK=16, 256 threads, 8x8 register tile.
// ---------------------------------------------------------------------------
__global__ __launch_bounds__(256, 2)
void gemm_nt_bias(const float* __restrict__ A, const float* __restrict__ Bm,
                  const float* __restrict__ bias, float* __restrict__ C,
                  int M, int N, int K)
{
    __shared__ float As[16][132];
    __shared__ float Bs[16][132];

    const int tid = threadIdx.x;
    const int bm  = blockIdx.y * 128;
    const int bn  = blockIdx.x * 128;
    const int tx  = tid & 15;       // col group
    const int ty  = tid >> 4;       // row group
    const int lrow = tid >> 2;      // 0..63
    const int lk4  = (tid & 3) << 2; // 0,4,8,12

    float acc[8][8];
#pragma unroll
    for (int i = 0; i < 8; i++)
#pragma unroll
        for (int j = 0; j < 8; j++) acc[i][j] = 0.0f;

    for (int k0 = 0; k0 < K; k0 += 16) {
        __syncthreads();
#pragma unroll
        for (int it = 0; it < 2; it++) {
            int r = lrow + it * 64;
            float4 va = *(const float4*)(A + (size_t)(bm + r) * K + k0 + lk4);
            As[lk4 + 0][r] = va.x; As[lk4 + 1][r] = va.y;
            As[lk4 + 2][r] = va.z; As[lk4 + 3][r] = va.w;
            float4 vb = *(const float4*)(Bm + (size_t)(bn + r) * K + k0 + lk4);
            Bs[lk4 + 0][r] = vb.x; Bs[lk4 + 1][r] = vb.y;
            Bs[lk4 + 2][r] = vb.z; Bs[lk4 + 3][r] = vb.w;
        }
        __syncthreads();
#pragma unroll
        for (int k = 0; k < 16; k++) {
            float4 a0 = *(const float4*)&As[k][ty * 8];
            float4 a1 = *(const float4*)&As[k][ty * 8 + 4];
            float4 b0 = *(const float4*)&Bs[k][tx * 8];
            float4 b1 = *(const float4*)&Bs[k][tx * 8 + 4];
            float a[8] = {a0.x, a0.y, a0.z, a0.w, a1.x, a1.y, a1.z, a1.w};
            float b[8] = {b0.x, b0.y, b0.z, b0.w, b1.x, b1.y, b1.z, b1.w};
#pragma unroll
            for (int i = 0; i < 8; i++)
#pragma unroll
                for (int j = 0; j < 8; j++)
                    acc[i][j] += a[i] * b[j];
        }
    }

    // Epilogue with bias
    float bv[8];
#pragma unroll
    for (int j = 0; j < 8; j++) bv[j] = bias[bn + tx * 8 + j];
#pragma unroll
    for (int i = 0; i < 8; i++) {
        float* crow = C + (size_t)(bm + ty * 8 + i) * N + bn + tx * 8;
        float4 o0 = make_float4(acc[i][0] + bv[0], acc[i][1] + bv[1],
                                acc[i][2] + bv[2], acc[i][3] + bv[3]);
        float4 o1 = make_float4(acc[i][4] + bv[4], acc[i][5] + bv[5],
                                acc[i][6] + bv[6], acc[i][7] + bv[7]);
        *(float4*)(crow)     = o0;
        *(float4*)(crow + 4) = o1;
    }
}

// ---------------------------------------------------------------------------
// Fused attention (NO softmax): per (b,h,q-tile 128):
//   loop k-tiles of 128: S = Q K^T / 8 ; S = mask ? S : 1e-9 ; O += S V
// smem: Qs[d][q] Ks[d][k] (transposed, pitch 132), Vs[k][d] (pitch 68),
//        Ss[q][k] (pitch 132). Total ~166 KB dynamic.
// ---------------------------------------------------------------------------
#define QP 132
#define VP 68
#define SMEM_ATT ((64 * QP + 64 * QP + 128 * VP + 128 * QP) * 4)

__global__ __launch_bounds__(256, 1)
void attn_kernel(const float* __restrict__ Q, const float* __restrict__ Kb,
                 const float* __restrict__ V, const int* __restrict__ mask,
                 float* __restrict__ O)
{
    extern __shared__ float sm[];
    float* Qs = sm;                    // [64][QP]  (d-major, q inner)
    float* Ks = Qs + 64 * QP;          // [64][QP]  (d-major, k inner)
    float* Vs = Ks + 64 * QP;          // [128][VP] (k-major, d inner)
    float* Ss = Vs + 128 * VP;         // [128][QP] (q-major, k inner)

    const int tid = threadIdx.x;
    const int q0  = blockIdx.x * 128;
    const int bh  = blockIdx.y;
    const int b   = bh >> 4;
    const int h   = bh & 15;
    const int hoff = h * DHD;

    const int tx  = tid & 15, ty  = tid >> 4;   // gemm1: 8x8 tile
    const int tx2 = tid & 7,  ty2 = tid >> 3;   // gemm2: rows ty2*4, cols tx2*8

    // Load Q tile transposed: Qs[d][q]
#pragma unroll
    for (int it = 0; it < 8; it++) {
        int idx = tid + it * 256;
        int r   = idx >> 4;             // 0..127
        int d4  = (idx & 15) << 2;      // 0..60
        float4 v = *(const float4*)(Q + (size_t)(b * SS + q0 + r) * EE + hoff + d4);
        Qs[(d4 + 0) * QP + r] = v.x;
        Qs[(d4 + 1) * QP + r] = v.y;
        Qs[(d4 + 2) * QP + r] = v.z;
        Qs[(d4 + 3) * QP + r] = v.w;
    }

    float acc2[4][8];
#pragma unroll
    for (int i = 0; i < 4; i++)
#pragma unroll
        for (int j = 0; j < 8; j++) acc2[i][j] = 0.0f;

    for (int kt = 0; kt < 16; kt++) {
        const int k0 = kt * 128;
        __syncthreads();   // prev iteration's gemm2 done -> safe to overwrite Ks/Vs/Ss
        // Load K tile transposed + V tile natural
#pragma unroll
        for (int it = 0; it < 8; it++) {
            int idx = tid + it * 256;
            int r   = idx >> 4;
            int d4  = (idx & 15) << 2;
            float4 v = *(const float4*)(Kb + (size_t)(b * SS + k0 + r) * EE + hoff + d4);
            Ks[(d4 + 0) * QP + r] = v.x;
            Ks[(d4 + 1) * QP + r] = v.y;
            Ks[(d4 + 2) * QP + r] = v.z;
            Ks[(d4 + 3) * QP + r] = v.w;
            float4 w = *(const float4*)(V + (size_t)(b * SS + k0 + r) * EE + hoff + d4);
            *(float4*)&Vs[r * VP + d4] = w;
        }
        __syncthreads();

        // gemm1: S[128,128] = Q[128,64] * K[128,64]^T
        float acc[8][8];
#pragma unroll
        for (int i = 0; i < 8; i++)
#pragma unroll
            for (int j = 0; j < 8; j++) acc[i][j] = 0.0f;

#pragma unroll 16
        for (int d = 0; d < 64; d++) {
            float4 a0 = *(const float4*)&Qs[d * QP + ty * 8];
            float4 a1 = *(const float4*)&Qs[d * QP + ty * 8 + 4];
            float4 b0 = *(const float4*)&Ks[d * QP + tx * 8];
            float4 b1 = *(const float4*)&Ks[d * QP + tx * 8 + 4];
            float a[8] = {a0.x, a0.y, a0.z, a0.w, a1.x, a1.y, a1.z, a1.w};
            float bb2[8] = {b0.x, b0.y, b0.z, b0.w, b1.x, b1.y, b1.z, b1.w};
#pragma unroll
            for (int i = 0; i < 8; i++)
#pragma unroll
                for (int j = 0; j < 8; j++)
                    acc[i][j] += a[i] * bb2[j];
        }

        // scale 1/sqrt(DH)=0.125, apply mask (mask==0 -> 1e-9), store to Ss
#pragma unroll
        for (int i = 0; i < 8; i++) {
            int qg = q0 + ty * 8 + i;
            const int* mrow = mask + ((size_t)b * SS + qg) * SS + k0 + tx * 8;
            int4 m0 = *(const int4*)mrow;
            int4 m1 = *(const int4*)(mrow + 4);
            float s0 = m0.x ? acc[i][0] * 0.125f : 1e-9f;
            float s1 = m0.y ? acc[i][1] * 0.125f : 1e-9f;
            float s2 = m0.z ? acc[i][2] * 0.125f : 1e-9f;
            float s3 = m0.w ? acc[i][3] * 0.125f : 1e-9f;
            float s4 = m1.x ? acc[i][4] * 0.125f : 1e-9f;
            float s5 = m1.y ? acc[i][5] * 0.125f : 1e-9f;
            float s6 = m1.z ? acc[i][6] * 0.125f : 1e-9f;
            float s7 = m1.w ? acc[i][7] * 0.125f : 1e-9f;
            *(float4*)&Ss[(ty * 8 + i) * QP + tx * 8]     = make_float4(s0, s1, s2, s3);
            *(float4*)&Ss[(ty * 8 + i) * QP + tx * 8 + 4] = make_float4(s4, s5, s6, s7);
        }
        __syncthreads();

        // gemm2: O[128,64] += S[128,128] * V[128,64]
#pragma unroll 8
        for (int kk = 0; kk < 128; kk++) {
            float4 b0 = *(const float4*)&Vs[kk * VP + tx2 * 8];
            float4 b1 = *(const float4*)&Vs[kk * VP + tx2 * 8 + 4];
            float bv[8] = {b0.x, b0.y, b0.z, b0.w, b1.x, b1.y, b1.z, b1.w};
#pragma unroll
            for (int i = 0; i < 4; i++) {
                float a = Ss[(ty2 * 4 + i) * QP + kk];
#pragma unroll
                for (int j = 0; j < 8; j++)
                    acc2[i][j] += a * bv[j];
            }
        }
    }

    // Epilogue: write O tile to merged-head layout [B,S,E]
#pragma unroll
    for (int i = 0; i < 4; i++) {
        float* orow = O + (size_t)(b * SS + q0 + ty2 * 4 + i) * EE + hoff + tx2 * 8;
        *(float4*)(orow)     = make_float4(acc2[i][0], acc2[i][1], acc2[i][2], acc2[i][3]);
        *(float4*)(orow + 4) = make_float4(acc2[i][4], acc2[i][5], acc2[i][6], acc2[i][7]);
    }
}

// ---------------------------------------------------------------------------
extern "C" void kernel_launch(void* const* d_in, const int* in_sizes, int n_in,
                              void* d_out, int out_size)
{
    const float* query = (const float*)d_in[0];
    const float* key   = (const float*)d_in[1];
    const float* value = (const float*)d_in[2];
    const int*   mask  = (const int*)  d_in[3];
    const float* Wq    = (const float*)d_in[4];
    const float* bq    = (const float*)d_in[5];
    const float* Wk    = (const float*)d_in[6];
    const float* bk    = (const float*)d_in[7];
    const float* Wv    = (const float*)d_in[8];
    const float* bv    = (const float*)d_in[9];
    const float* Wo    = (const float*)d_in[10];
    const float* bo    = (const float*)d_in[11];
    float* out = (float*)d_out;

    float *gq, *gk, *gv, *go;
    cudaGetSymbolAddress((void**)&gq, g_q);
    cudaGetSymbolAddress((void**)&gk, g_k);
    cudaGetSymbolAddress((void**)&gv, g_v);
    cudaGetSymbolAddress((void**)&go, g_o);

    const int M = BB * SS;   // 4096
    dim3 pgrid(EE / 128, M / 128);   // (8, 32)

    gemm_nt_bias<<<pgrid, 256>>>(query, Wq, bq, gq, M, EE, EE);
    gemm_nt_bias<<<pgrid, 256>>>(key,   Wk, bk, gk, M, EE, EE);
    gemm_nt_bias<<<pgrid, 256>>>(value, Wv, bv, gv, M, EE, EE);

    cudaFuncSetAttribute(attn_kernel, cudaFuncAttributeMaxDynamicSharedMemorySize, SMEM_ATT);
    dim3 agrid(SS / 128, BB * HH);   // (16, 32)
    attn_kernel<<<agrid, 256, SMEM_ATT>>>(gq, gk, gv, mask, go);

    gemm_nt_bias<<<pgrid, 256>>>(go, Wo, bo, out, M, EE, EE);
}

// round 3
// speedup vs baseline: 1.0568x; 1.0568x over previous
#include <cuda_runtime.h>

// Problem constants (fixed shapes)
#define BB 2
#define SS 2048
#define EE 1024
#define HH 16
#define DHD 64

typedef unsigned long long u64;

// Packed f32x2 helpers (SASS FFMA2 — only reachable via PTX)
__device__ __forceinline__ u64 ffma2(u64 a, u64 b, u64 c) {
    u64 d;
    asm("fma.rn.f32x2 %0, %1, %2, %3;" : "=l"(d) : "l"(a), "l"(b), "l"(c));
    return d;
}
__device__ __forceinline__ u64 pack2(float x, float y) {
    u64 r;
    asm("mov.b64 %0, {%1, %2};" : "=l"(r) : "f"(x), "f"(y));
    return r;
}
__device__ __forceinline__ float2 unpack2(u64 v) {
    float2 f;
    asm("mov.b64 {%0, %1}, %2;" : "=f"(f.x), "=f"(f.y) : "l"(v));
    return f;
}

// Scratch (allocation-free: __device__ globals). 4 x 16 MB.
__device__ float g_q[BB * SS * EE];
__device__ float g_k[BB * SS * EE];
__device__ float g_v[BB * SS * EE];
__device__ float g_o[BB * SS * EE];

// ---------------------------------------------------------------------------
// GEMM: C[M,N] = A[M,K] * B[N,K]^T + bias[N]
// Block 128x128, BK=16, 256 threads, 8x8 register tile, FFMA2 inner product.
// ---------------------------------------------------------------------------
__global__ __launch_bounds__(256, 2)
void gemm_nt_bias(const float* __restrict__ A, const float* __restrict__ Bm,
                  const float* __restrict__ bias, float* __restrict__ C,
                  int M, int N, int K)
{
    __shared__ float As[16][132];
    __shared__ float Bs[16][132];

    const int tid = threadIdx.x;
    const int bm  = blockIdx.y * 128;
    const int bn  = blockIdx.x * 128;
    const int tx  = tid & 15;        // col group
    const int ty  = tid >> 4;        // row group
    const int lrow = tid >> 2;       // 0..63
    const int lk4  = (tid & 3) << 2; // 0,4,8,12

    u64 acc[8][4];
#pragma unroll
    for (int i = 0; i < 8; i++)
#pragma unroll
        for (int j = 0; j < 4; j++) acc[i][j] = 0ull;

    for (int k0 = 0; k0 < K; k0 += 16) {
        __syncthreads();
#pragma unroll
        for (int it = 0; it < 2; it++) {
            int r = lrow + it * 64;
            float4 va = *(const float4*)(A + (size_t)(bm + r) * K + k0 + lk4);
            As[lk4 + 0][r] = va.x; As[lk4 + 1][r] = va.y;
            As[lk4 + 2][r] = va.z; As[lk4 + 3][r] = va.w;
            float4 vb = *(const float4*)(Bm + (size_t)(bn + r) * K + k0 + lk4);
            Bs[lk4 + 0][r] = vb.x; Bs[lk4 + 1][r] = vb.y;
            Bs[lk4 + 2][r] = vb.z; Bs[lk4 + 3][r] = vb.w;
        }
        __syncthreads();
#pragma unroll
        for (int k = 0; k < 16; k++) {
            float4 a0 = *(const float4*)&As[k][ty * 8];
            float4 a1 = *(const float4*)&As[k][ty * 8 + 4];
            ulonglong2 bA = *(const ulonglong2*)&Bs[k][tx * 8];
            ulonglong2 bB = *(const ulonglong2*)&Bs[k][tx * 8 + 4];
            float a[8] = {a0.x, a0.y, a0.z, a0.w, a1.x, a1.y, a1.z, a1.w};
#pragma unroll
            for (int i = 0; i < 8; i++) {
                u64 ap = pack2(a[i], a[i]);
                acc[i][0] = ffma2(ap, bA.x, acc[i][0]);
                acc[i][1] = ffma2(ap, bA.y, acc[i][1]);
                acc[i][2] = ffma2(ap, bB.x, acc[i][2]);
                acc[i][3] = ffma2(ap, bB.y, acc[i][3]);
            }
        }
    }

    // Epilogue with bias
    float bv[8];
#pragma unroll
    for (int j = 0; j < 8; j++) bv[j] = bias[bn + tx * 8 + j];
#pragma unroll
    for (int i = 0; i < 8; i++) {
        float2 c01 = unpack2(acc[i][0]);
        float2 c23 = unpack2(acc[i][1]);
        float2 c45 = unpack2(acc[i][2]);
        float2 c67 = unpack2(acc[i][3]);
        float* crow = C + (size_t)(bm + ty * 8 + i) * N + bn + tx * 8;
        *(float4*)(crow)     = make_float4(c01.x + bv[0], c01.y + bv[1],
                                           c23.x + bv[2], c23.y + bv[3]);
        *(float4*)(crow + 4) = make_float4(c45.x + bv[4], c45.y + bv[5],
                                           c67.x + bv[6], c67.y + bv[7]);
    }
}

// ---------------------------------------------------------------------------
// Fused attention (NO softmax): per (b,h,q-tile 128):
//   loop k-tiles of 128: S = Q K^T / 8 ; S = mask ? S : 1e-9 ; O += S V
// gemm1: 8x8 tiles (16x16 thread grid). gemm2: split-K over thread halves,
// each half 8x8 tiles over 64 k-values; one-time smem reduction at the end.
// ---------------------------------------------------------------------------
#define QP 132
#define VP 68
#define SMEM_ATT ((64 * QP + 64 * QP + 128 * VP + 128 * QP) * 4)

__global__ __launch_bounds__(256, 1)
void attn_kernel(const float* __restrict__ Q, const float* __restrict__ Kb,
                 const float* __restrict__ V, const int* __restrict__ mask,
                 float* __restrict__ O)
{
    extern __shared__ float sm[];
    float* Qs = sm;                    // [64][QP]  (d-major, q inner)
    float* Ks = Qs + 64 * QP;          // [64][QP]  (d-major, k inner)
    float* Vs = Ks + 64 * QP;          // [128][VP] (k-major, d inner)
    float* Ss = Vs + 128 * VP;         // [128][QP] (q-major, k inner); reused as reduce buf

    const int tid = threadIdx.x;
    const int q0  = blockIdx.x * 128;
    const int bh  = blockIdx.y;
    const int b   = bh >> 4;
    const int h   = bh & 15;
    const int hoff = h * DHD;

    const int tx = tid & 15, ty = tid >> 4;   // gemm1: 8x8 tile on 128x128
    // gemm2: split-K halves, 8(q) x 8(d) tile each
    const int half = tid >> 7;                // 0: k 0..63, 1: k 64..127
    const int tl   = tid & 127;
    const int rg   = tl >> 3;                 // q rows rg*8 .. +7
    const int cg   = tl & 7;                  // d cols cg*8 .. +7

    // Load Q tile transposed: Qs[d][q]
#pragma unroll
    for (int it = 0; it < 8; it++) {
        int idx = tid + it * 256;
        int r   = idx >> 4;             // 0..127
        int d4  = (idx & 15) << 2;      // 0..60
        float4 v = *(const float4*)(Q + (size_t)(b * SS + q0 + r) * EE + hoff + d4);
        Qs[(d4 + 0) * QP + r] = v.x;
        Qs[(d4 + 1) * QP + r] = v.y;
        Qs[(d4 + 2) * QP + r] = v.z;
        Qs[(d4 + 3) * QP + r] = v.w;
    }

    u64 acc2[8][4];
#pragma unroll
    for (int i = 0; i < 8; i++)
#pragma unroll
        for (int j = 0; j < 4; j++) acc2[i][j] = 0ull;

    for (int kt = 0; kt < 16; kt++) {
        const int k0 = kt * 128;
        __syncthreads();   // prev gemm2 done -> safe to overwrite Ks/Vs/Ss
#pragma unroll
        for (int it = 0; it < 8; it++) {
            int idx = tid + it * 256;
            int r   = idx >> 4;
            int d4  = (idx & 15) << 2;
            float4 v = *(const float4*)(Kb + (size_t)(b * SS + k0 + r) * EE + hoff + d4);
            Ks[(d4 + 0) * QP + r] = v.x;
            Ks[(d4 + 1) * QP + r] = v.y;
            Ks[(d4 + 2) * QP + r] = v.z;
            Ks[(d4 + 3) * QP + r] = v.w;
            float4 w = *(const float4*)(V + (size_t)(b * SS + k0 + r) * EE + hoff + d4);
            *(float4*)&Vs[r * VP + d4] = w;
        }
        __syncthreads();

        // gemm1: S[128,128] = Q[128,64] * K[128,64]^T  (FFMA2)
        u64 acc1[8][4];
#pragma unroll
        for (int i = 0; i < 8; i++)
#pragma unroll
            for (int j = 0; j < 4; j++) acc1[i][j] = 0ull;

#pragma unroll 16
        for (int d = 0; d < 64; d++) {
            float4 a0 = *(const float4*)&Qs[d * QP + ty * 8];
            float4 a1 = *(const float4*)&Qs[d * QP + ty * 8 + 4];
            ulonglong2 bA = *(const ulonglong2*)&Ks[d * QP + tx * 8];
            ulonglong2 bB = *(const ulonglong2*)&Ks[d * QP + tx * 8 + 4];
            float a[8] = {a0.x, a0.y, a0.z, a0.w, a1.x, a1.y, a1.z, a1.w};
#pragma unroll
            for (int i = 0; i < 8; i++) {
                u64 ap = pack2(a[i], a[i]);
                acc1[i][0] = ffma2(ap, bA.x, acc1[i][0]);
                acc1[i][1] = ffma2(ap, bA.y, acc1[i][1]);
                acc1[i][2] = ffma2(ap, bB.x, acc1[i][2]);
                acc1[i][3] = ffma2(ap, bB.y, acc1[i][3]);
            }
        }

        // scale 1/sqrt(DH)=0.125, apply mask (mask==0 -> 1e-9), store to Ss
#pragma unroll
        for (int i = 0; i < 8; i++) {
            int qg = q0 + ty * 8 + i;
            const int* mrow = mask + ((size_t)b * SS + qg) * SS + k0 + tx * 8;
            int4 m0 = *(const int4*)mrow;
            int4 m1 = *(const int4*)(mrow + 4);
            float2 c01 = unpack2(acc1[i][0]);
            float2 c23 = unpack2(acc1[i][1]);
            float2 c45 = unpack2(acc1[i][2]);
            float2 c67 = unpack2(acc1[i][3]);
            float s0 = m0.x ? c01.x * 0.125f : 1e-9f;
            float s1 = m0.y ? c01.y * 0.125f : 1e-9f;
            float s2 = m0.z ? c23.x * 0.125f : 1e-9f;
            float s3 = m0.w ? c23.y * 0.125f : 1e-9f;
            float s4 = m1.x ? c45.x * 0.125f : 1e-9f;
            float s5 = m1.y ? c45.y * 0.125f : 1e-9f;
            float s6 = m1.z ? c67.x * 0.125f : 1e-9f;
            float s7 = m1.w ? c67.y * 0.125f : 1e-9f;
            *(float4*)&Ss[(ty * 8 + i) * QP + tx * 8]     = make_float4(s0, s1, s2, s3);
            *(float4*)&Ss[(ty * 8 + i) * QP + tx * 8 + 4] = make_float4(s4, s5, s6, s7);
        }
        __syncthreads();

        // gemm2: O[128,64] += S[128,128] * V[128,64]  (split-K, 8x8, FFMA2)
        const int kbase = half * 64;
#pragma unroll 4
        for (int kk = 0; kk < 64; kk += 4) {
            const int kr = kbase + kk;
            ulonglong2 v0a = *(const ulonglong2*)&Vs[(kr + 0) * VP + cg * 8];
            ulonglong2 v0b = *(const ulonglong2*)&Vs[(kr + 0) * VP + cg * 8 + 4];
            ulonglong2 v1a = *(const ulonglong2*)&Vs[(kr + 1) * VP + cg * 8];
            ulonglong2 v1b = *(const ulonglong2*)&Vs[(kr + 1) * VP + cg * 8 + 4];
            ulonglong2 v2a = *(const ulonglong2*)&Vs[(kr + 2) * VP + cg * 8];
            ulonglong2 v2b = *(const ulonglong2*)&Vs[(kr + 2) * VP + cg * 8 + 4];
            ulonglong2 v3a = *(const ulonglong2*)&Vs[(kr + 3) * VP + cg * 8];
            ulonglong2 v3b = *(const ulonglong2*)&Vs[(kr + 3) * VP + cg * 8 + 4];
#pragma unroll
            for (int r = 0; r < 8; r++) {
                float4 s = *(const float4*)&Ss[(rg * 8 + r) * QP + kr];
                u64 ap;
                ap = pack2(s.x, s.x);
                acc2[r][0] = ffma2(ap, v0a.x, acc2[r][0]);
                acc2[r][1] = ffma2(ap, v0a.y, acc2[r][1]);
                acc2[r][2] = ffma2(ap, v0b.x, acc2[r][2]);
                acc2[r][3] = ffma2(ap, v0b.y, acc2[r][3]);
                ap = pack2(s.y, s.y);
                acc2[r][0] = ffma2(ap, v1a.x, acc2[r][0]);
                acc2[r][1] = ffma2(ap, v1a.y, acc2[r][1]);
                acc2[r][2] = ffma2(ap, v1b.x, acc2[r][2]);
                acc2[r][3] = ffma2(ap, v1b.y, acc2[r][3]);
                ap = pack2(s.z, s.z);
                acc2[r][0] = ffma2(ap, v2a.x, acc2[r][0]);
                acc2[r][1] = ffma2(ap, v2a.y, acc2[r][1]);
                acc2[r][2] = ffma2(ap, v2b.x, acc2[r][2]);
                acc2[r][3] = ffma2(ap, v2b.y, acc2[r][3]);
                ap = pack2(s.w, s.w);
                acc2[r][0] = ffma2(ap, v3a.x, acc2[r][0]);
                acc2[r][1] = ffma2(ap, v3a.y, acc2[r][1]);
                acc2[r][2] = ffma2(ap, v3b.x, acc2[r][2]);
                acc2[r][3] = ffma2(ap, v3b.y, acc2[r][3]);
            }
        }
    }

    // Reduce the two k-halves (reuse Ss as [128][VP] float buffer) and write O.
    __syncthreads();
    if (half == 1) {
#pragma unroll
        for (int r = 0; r < 8; r++) {
            float2 c01 = unpack2(acc2[r][0]);
            float2 c23 = unpack2(acc2[r][1]);
            float2 c45 = unpack2(acc2[r][2]);
            float2 c67 = unpack2(acc2[r][3]);
            float* dst = &Ss[(rg * 8 + r) * VP + cg * 8];
            *(float4*)(dst)     = make_float4(c01.x, c01.y, c23.x, c23.y);
            *(float4*)(dst + 4) = make_float4(c45.x, c45.y, c67.x, c67.y);
        }
    }
    __syncthreads();
    if (half == 0) {
#pragma unroll
        for (int r = 0; r < 8; r++) {
            float2 c01 = unpack2(acc2[r][0]);
            float2 c23 = unpack2(acc2[r][1]);
            float2 c45 = unpack2(acc2[r][2]);
            float2 c67 = unpack2(acc2[r][3]);
            const float* src = &Ss[(rg * 8 + r) * VP + cg * 8];
            float4 p0 = *(const float4*)(src);
            float4 p1 = *(const float4*)(src + 4);
            float* orow = O + (size_t)(b * SS + q0 + rg * 8 + r) * EE + hoff + cg * 8;
            *(float4*)(orow)     = make_float4(c01.x + p0.x, c01.y + p0.y,
                                               c23.x + p0.z, c23.y + p0.w);
            *(float4*)(orow + 4) = make_float4(c45.x + p1.x, c45.y + p1.y,
                                               c67.x + p1.z, c67.y + p1.w);
        }
    }
}

// ---------------------------------------------------------------------------
extern "C" void kernel_launch(void* const* d_in, const int* in_sizes, int n_in,
                              void* d_out, int out_size)
{
    const float* query = (const float*)d_in[0];
    const float* key   = (const float*)d_in[1];
    const float* value = (const float*)d_in[2];
    const int*   mask  = (const int*)  d_in[3];
    const float* Wq    = (const float*)d_in[4];
    const float* bq    = (const float*)d_in[5];
    const float* Wk    = (const float*)d_in[6];
    const float* bk    = (const float*)d_in[7];
    const float* Wv    = (const float*)d_in[8];
    const float* bv    = (const float*)d_in[9];
    const float* Wo    = (const float*)d_in[10];
    const float* bo    = (const float*)d_in[11];
    float* out = (float*)d_out;

    float *gq, *gk, *gv, *go;
    cudaGetSymbolAddress((void**)&gq, g_q);
    cudaGetSymbolAddress((void**)&gk, g_k);
    cudaGetSymbolAddress((void**)&gv, g_v);
    cudaGetSymbolAddress((void**)&go, g_o);

    const int M = BB * SS;   // 4096
    dim3 pgrid(EE / 128, M / 128);   // (8, 32)

    gemm_nt_bias<<<pgrid, 256>>>(query, Wq, bq, gq, M, EE, EE);
    gemm_nt_bias<<<pgrid, 256>>>(key,   Wk, bk, gk, M, EE, EE);
    gemm_nt_bias<<<pgrid, 256>>>(value, Wv, bv, gv, M, EE, EE);

    cudaFuncSetAttribute(attn_kernel, cudaFuncAttributeMaxDynamicSharedMemorySize, SMEM_ATT);
    dim3 agrid(SS / 128, BB * HH);   // (16, 32)
    attn_kernel<<<agrid, 256, SMEM_ATT>>>(gq, gk, gv, mask, go);

    gemm_nt_bias<<<pgrid, 256>>>(go, Wo, bo, out, M, EE, EE);
}

// round 5
// speedup vs baseline: 2.5451x; 2.4083x over previous
#include <cuda_runtime.h>
#include <cstdint>

// Problem constants (fixed shapes)
#define BB 2
#define SS 2048
#define EE 1024
#define HH 16
#define DHD 64

// ---------------------------------------------------------------------------
// PTX helpers (all non-'a' features: work on compute_103 base target)
// ---------------------------------------------------------------------------
__device__ __forceinline__ uint32_t smem_u32(const void* p) {
    uint32_t a;
    asm("{ .reg .u64 t; cvta.to.shared.u64 t, %1; cvt.u32.u64 %0, t; }" : "=r"(a) : "l"(p));
    return a;
}
__device__ __forceinline__ void ldsm4(uint32_t r[4], uint32_t a) {
    asm volatile("ldmatrix.sync.aligned.m8n8.x4.shared.b16 {%0,%1,%2,%3}, [%4];"
                 : "=r"(r[0]), "=r"(r[1]), "=r"(r[2]), "=r"(r[3]) : "r"(a));
}
__device__ __forceinline__ void ldsm4t(uint32_t r[4], uint32_t a) {
    asm volatile("ldmatrix.sync.aligned.m8n8.x4.trans.shared.b16 {%0,%1,%2,%3}, [%4];"
                 : "=r"(r[0]), "=r"(r[1]), "=r"(r[2]), "=r"(r[3]) : "r"(a));
}
__device__ __forceinline__ void mma_bf16(float d[4], const uint32_t a[4], const uint32_t b[2]) {
    asm volatile("mma.sync.aligned.m16n8k16.row.col.f32.bf16.bf16.f32 "
                 "{%0,%1,%2,%3}, {%4,%5,%6,%7}, {%8,%9}, {%0,%1,%2,%3};"
                 : "+f"(d[0]), "+f"(d[1]), "+f"(d[2]), "+f"(d[3])
                 : "r"(a[0]), "r"(a[1]), "r"(a[2]), "r"(a[3]), "r"(b[0]), "r"(b[1]));
}
// split fp32 pair -> bf16x2 hi + bf16x2 lo (x = hi + lo, exact residual)
__device__ __forceinline__ void split2(float2 v, uint32_t& hi, uint32_t& lo) {
    asm("cvt.rn.bf16x2.f32 %0, %1, %2;" : "=r"(hi) : "f"(v.y), "f"(v.x));
    float h0 = __uint_as_float(hi << 16);
    float h1 = __uint_as_float(hi & 0xFFFF0000u);
    asm("cvt.rn.bf16x2.f32 %0, %1, %2;" : "=r"(lo) : "f"(v.y - h1), "f"(v.x - h0));
}

// Scratch (allocation-free: __device__ globals). 4 x 16 MB.
__device__ float g_q[BB * SS * EE];
__device__ float g_k[BB * SS * EE];
__device__ float g_v[BB * SS * EE];
__device__ float g_o[BB * SS * EE];

// ---------------------------------------------------------------------------
// Projection GEMM: C[M,N] = A[M,K]*B[N,K]^T + bias. bf16 2-term split, 3 MMA
// terms, fp32 accum. Tile 128x128, BK=64, 256 threads (8 warps, 2x4 grid).
// smem: Ahi/Alo/Bhi/Blo [128][72] bf16 (pad 72 => 144B stride, ldsm conflict-free)
// ---------------------------------------------------------------------------
#define GP 72
#define GPB 144
#define O_AHI 0
#define O_ALO 18432
#define O_BHI 36864
#define O_BLO 55296
#define PRJ_SMEM 73728

__global__ __launch_bounds__(256, 2)
void gemm_mma(const float* __restrict__ A, const float* __restrict__ W,
              const float* __restrict__ bias, float* __restrict__ C)
{
    extern __shared__ char sm[];
    const uint32_t smb = smem_u32(sm);
    const int tid = threadIdx.x;
    const int bm = blockIdx.y * 128, bn = blockIdx.x * 128;
    const int w = tid >> 5, lane = tid & 31;
    const int m0 = (w & 1) * 64, n0 = (w >> 1) * 32;
    const int r8 = lane & 7, quad = lane >> 3;
    const int arow = (quad & 1) * 8 + r8, acol = (quad >> 1) * 8;
    const int brow = (quad >> 1) * 8 + r8, bcol = (quad & 1) * 8;

    float acc[4][4][4];
#pragma unroll
    for (int i = 0; i < 4; i++)
#pragma unroll
        for (int j = 0; j < 4; j++)
#pragma unroll
            for (int k = 0; k < 4; k++) acc[i][j][k] = 0.0f;

    for (int s = 0; s < 16; s++) {
        const int kk0 = s << 6;
        __syncthreads();
        // convert fp32 -> bf16 hi/lo tiles
#pragma unroll
        for (int it = 0; it < 16; it++) {
            int p = tid + it * 256, row = p >> 5, pc = p & 31;
            uint32_t off = (uint32_t)(row * GPB + pc * 4);
            float2 av = *(const float2*)(A + (size_t)(bm + row) * EE + kk0 + pc * 2);
            uint32_t hi, lo;
            split2(av, hi, lo);
            *(uint32_t*)(sm + O_AHI + off) = hi;
            *(uint32_t*)(sm + O_ALO + off) = lo;
            float2 wv = *(const float2*)(W + (size_t)(bn + row) * EE + kk0 + pc * 2);
            split2(wv, hi, lo);
            *(uint32_t*)(sm + O_BHI + off) = hi;
            *(uint32_t*)(sm + O_BLO + off) = lo;
        }
        __syncthreads();

#pragma unroll
        for (int kf = 0; kf < 4; kf++) {
            uint32_t bh[4][2], bl[4][2], t[4];
#pragma unroll
            for (int np = 0; np < 2; np++) {
                uint32_t boff = (uint32_t)((n0 + np * 16 + brow) * GP + kf * 16 + bcol) * 2;
                ldsm4(t, smb + O_BHI + boff);
                bh[np * 2][0] = t[0]; bh[np * 2][1] = t[1];
                bh[np * 2 + 1][0] = t[2]; bh[np * 2 + 1][1] = t[3];
                ldsm4(t, smb + O_BLO + boff);
                bl[np * 2][0] = t[0]; bl[np * 2][1] = t[1];
                bl[np * 2 + 1][0] = t[2]; bl[np * 2 + 1][1] = t[3];
            }
#pragma unroll
            for (int mf = 0; mf < 4; mf++) {
                uint32_t ah[4], al[4];
                uint32_t aoff = (uint32_t)((m0 + mf * 16 + arow) * GP + kf * 16 + acol) * 2;
                ldsm4(ah, smb + O_AHI + aoff);
                ldsm4(al, smb + O_ALO + aoff);
#pragma unroll
                for (int nf = 0; nf < 4; nf++) {
                    mma_bf16(acc[mf][nf], ah, bh[nf]);
                    mma_bf16(acc[mf][nf], ah, bl[nf]);
                    mma_bf16(acc[mf][nf], al, bh[nf]);
                }
            }
        }
    }

    // epilogue
    const int g = lane >> 2, t2 = (lane & 3) * 2;
#pragma unroll
    for (int mf = 0; mf < 4; mf++)
#pragma unroll
        for (int nf = 0; nf < 4; nf++) {
            int row0 = bm + m0 + mf * 16 + g;
            int col = bn + n0 + nf * 8 + t2;
            float b0 = bias[col], b1 = bias[col + 1];
            *(float2*)(C + (size_t)row0 * EE + col) =
                make_float2(acc[mf][nf][0] + b0, acc[mf][nf][1] + b1);
            *(float2*)(C + (size_t)(row0 + 8) * EE + col) =
                make_float2(acc[mf][nf][2] + b0, acc[mf][nf][3] + b1);
        }
}

// ---------------------------------------------------------------------------
// Fused attention, tensor-core version (NO softmax):
// per (b,h,q-tile 128): loop 16 k-tiles of 128:
//   S = QK^T/8 (MMA, split) -> mask -> store S as bf16 hi/lo -> O += S V (MMA)
// Q/K/V tiles [128][72] bf16 hi+lo; S [128][136] bf16 hi+lo.
// V kept in natural [k][d] layout; B-fragments via ldmatrix.trans.
// ---------------------------------------------------------------------------
#define SP  136
#define SPB 272
#define AQHI 0
#define AQLO 18432
#define AKHI 36864
#define AKLO 55296
#define AVHI 73728
#define AVLO 92160
#define ASHI 110592
#define ASLO 145408
#define ATT_SMEM 180224

__global__ __launch_bounds__(256, 1)
void attn_mma(const float* __restrict__ Q, const float* __restrict__ Kg,
              const float* __restrict__ Vg, const int* __restrict__ mask,
              float* __restrict__ O)
{
    extern __shared__ char sm[];
    const uint32_t smb = smem_u32(sm);
    const int tid = threadIdx.x;
    const int q0 = blockIdx.x * 128;
    const int bh = blockIdx.y, b = bh >> 4, h = bh & 15, hoff = h * DHD;
    const int w = tid >> 5, lane = tid & 31;
    const int m0 = (w & 1) * 64, wn = w >> 1;
    const int n0 = wn * 32;
    const int r8 = lane & 7, quad = lane >> 3;
    const int arow = (quad & 1) * 8 + r8, acol = (quad >> 1) * 8;
    const int brow = (quad >> 1) * 8 + r8, bcol = (quad & 1) * 8;
    const int g = lane >> 2, t2 = (lane & 3) * 2;

    // convert Q tile once
#pragma unroll
    for (int it = 0; it < 16; it++) {
        int p = tid + it * 256, row = p >> 5, pc = p & 31;
        uint32_t off = (uint32_t)(row * GPB + pc * 4);
        float2 v = *(const float2*)(Q + (size_t)(b * SS + q0 + row) * EE + hoff + pc * 2);
        uint32_t hi, lo;
        split2(v, hi, lo);
        *(uint32_t*)(sm + AQHI + off) = hi;
        *(uint32_t*)(sm + AQLO + off) = lo;
    }

    float acc2[4][2][4];
#pragma unroll
    for (int i = 0; i < 4; i++)
#pragma unroll
        for (int j = 0; j < 2; j++)
#pragma unroll
            for (int k = 0; k < 4; k++) acc2[i][j][k] = 0.0f;

    for (int kt = 0; kt < 16; kt++) {
        const int k0 = kt * 128;
        __syncthreads();
        // convert K, V tiles
#pragma unroll
        for (int it = 0; it < 16; it++) {
            int p = tid + it * 256, row = p >> 5, pc = p & 31;
            uint32_t off = (uint32_t)(row * GPB + pc * 4);
            float2 kv = *(const float2*)(Kg + (size_t)(b * SS + k0 + row) * EE + hoff + pc * 2);
            uint32_t hi, lo;
            split2(kv, hi, lo);
            *(uint32_t*)(sm + AKHI + off) = hi;
            *(uint32_t*)(sm + AKLO + off) = lo;
            float2 vv = *(const float2*)(Vg + (size_t)(b * SS + k0 + row) * EE + hoff + pc * 2);
            split2(vv, hi, lo);
            *(uint32_t*)(sm + AVHI + off) = hi;
            *(uint32_t*)(sm + AVLO + off) = lo;
        }
        __syncthreads();

        // gemm1: S = Q K^T (k-dim 64 -> 4 ksteps)
        float acc1[4][4][4];
#pragma unroll
        for (int i = 0; i < 4; i++)
#pragma unroll
            for (int j = 0; j < 4; j++)
#pragma unroll
                for (int k = 0; k < 4; k++) acc1[i][j][k] = 0.0f;

#pragma unroll
        for (int kf = 0; kf < 4; kf++) {
            uint32_t bh_[4][2], bl_[4][2], t[4];
#pragma unroll
            for (int np = 0; np < 2; np++) {
                uint32_t boff = (uint32_t)((n0 + np * 16 + brow) * GP + kf * 16 + bcol) * 2;
                ldsm4(t, smb + AKHI + boff);
                bh_[np * 2][0] = t[0]; bh_[np * 2][1] = t[1];
                bh_[np * 2 + 1][0] = t[2]; bh_[np * 2 + 1][1] = t[3];
                ldsm4(t, smb + AKLO + boff);
                bl_[np * 2][0] = t[0]; bl_[np * 2][1] = t[1];
                bl_[np * 2 + 1][0] = t[2]; bl_[np * 2 + 1][1] = t[3];
            }
#pragma unroll
            for (int mf = 0; mf < 4; mf++) {
                uint32_t ah[4], al[4];
                uint32_t aoff = (uint32_t)((m0 + mf * 16 + arow) * GP + kf * 16 + acol) * 2;
                ldsm4(ah, smb + AQHI + aoff);
                ldsm4(al, smb + AQLO + aoff);
#pragma unroll
                for (int nf = 0; nf < 4; nf++) {
                    mma_bf16(acc1[mf][nf], ah, bh_[nf]);
                    mma_bf16(acc1[mf][nf], ah, bl_[nf]);
                    mma_bf16(acc1[mf][nf], al, bh_[nf]);
                }
            }
        }

        // scale + mask + store S (bf16 hi/lo)
#pragma unroll
        for (int mf = 0; mf < 4; mf++)
#pragma unroll
            for (int nf = 0; nf < 4; nf++) {
                int rl = m0 + mf * 16 + g;
                int cl = n0 + nf * 8 + t2;
                const int* mp = mask + ((size_t)b * SS + q0 + rl) * SS + k0 + cl;
                int2 ma = *(const int2*)mp;
                int2 mb = *(const int2*)(mp + (size_t)8 * SS);
                float v0 = ma.x ? acc1[mf][nf][0] * 0.125f : 1e-9f;
                float v1 = ma.y ? acc1[mf][nf][1] * 0.125f : 1e-9f;
                float v2 = mb.x ? acc1[mf][nf][2] * 0.125f : 1e-9f;
                float v3 = mb.y ? acc1[mf][nf][3] * 0.125f : 1e-9f;
                uint32_t hi, lo;
                split2(make_float2(v0, v1), hi, lo);
                *(uint32_t*)(sm + ASHI + rl * SPB + cl * 2) = hi;
                *(uint32_t*)(sm + ASLO + rl * SPB + cl * 2) = lo;
                split2(make_float2(v2, v3), hi, lo);
                *(uint32_t*)(sm + ASHI + (rl + 8) * SPB + cl * 2) = hi;
                *(uint32_t*)(sm + ASLO + (rl + 8) * SPB + cl * 2) = lo;
            }
        __syncthreads();

        // gemm2: O += S V  (k-dim 128 -> 8 ksteps; warp covers d cols wn*16..+15)
#pragma unroll
        for (int kf = 0; kf < 8; kf++) {
            uint32_t bhf[2][2], blf[2][2], t[4];
            uint32_t voff = (uint32_t)((kf * 16 + (quad & 1) * 8 + r8) * GP +
                                       wn * 16 + (quad >> 1) * 8) * 2;
            ldsm4t(t, smb + AVHI + voff);
            bhf[0][0] = t[0]; bhf[0][1] = t[1]; bhf[1][0] = t[2]; bhf[1][1] = t[3];
            ldsm4t(t, smb + AVLO + voff);
            blf[0][0] = t[0]; blf[0][1] = t[1]; blf[1][0] = t[2]; blf[1][1] = t[3];
#pragma unroll
            for (int mf = 0; mf < 4; mf++) {
                uint32_t sh[4], sl[4];
                uint32_t soff = (uint32_t)((m0 + mf * 16 + arow) * SP + kf * 16 + acol) * 2;
                ldsm4(sh, smb + ASHI + soff);
                ldsm4(sl, smb + ASLO + soff);
#pragma unroll
                for (int nf = 0; nf < 2; nf++) {
                    mma_bf16(acc2[mf][nf], sh, bhf[nf]);
                    mma_bf16(acc2[mf][nf], sh, blf[nf]);
                    mma_bf16(acc2[mf][nf], sl, bhf[nf]);
                }
            }
        }
    }

    // epilogue: O tile -> merged-head layout [B,S,E]
#pragma unroll
    for (int mf = 0; mf < 4; mf++)
#pragma unroll
        for (int nf = 0; nf < 2; nf++) {
            int row = q0 + m0 + mf * 16 + g;
            int col = hoff + wn * 16 + nf * 8 + t2;
            *(float2*)(O + (size_t)(b * SS + row) * EE + col) =
                make_float2(acc2[mf][nf][0], acc2[mf][nf][1]);
            *(float2*)(O + (size_t)(b * SS + row + 8) * EE + col) =
                make_float2(acc2[mf][nf][2], acc2[mf][nf][3]);
        }
}

// ---------------------------------------------------------------------------
extern "C" void kernel_launch(void* const* d_in, const int* in_sizes, int n_in,
                              void* d_out, int out_size)
{
    const float* query = (const float*)d_in[0];
    const float* key   = (const float*)d_in[1];
    const float* value = (const float*)d_in[2];
    const int*   mask  = (const int*)  d_in[3];
    const float* Wq    = (const float*)d_in[4];
    const float* bq    = (const float*)d_in[5];
    const float* Wk    = (const float*)d_in[6];
    const float* bk    = (const float*)d_in[7];
    const float* Wv    = (const float*)d_in[8];
    const float* bv    = (const float*)d_in[9];
    const float* Wo    = (const float*)d_in[10];
    const float* bo    = (const float*)d_in[11];
    float* out = (float*)d_out;

    float *gq, *gk, *gv, *go;
    cudaGetSymbolAddress((void**)&gq, g_q);
    cudaGetSymbolAddress((void**)&gk, g_k);
    cudaGetSymbolAddress((void**)&gv, g_v);
    cudaGetSymbolAddress((void**)&go, g_o);

    cudaFuncSetAttribute(gemm_mma, cudaFuncAttributeMaxDynamicSharedMemorySize, PRJ_SMEM);
    cudaFuncSetAttribute(attn_mma, cudaFuncAttributeMaxDynamicSharedMemorySize, ATT_SMEM);

    dim3 pgrid(EE / 128, (BB * SS) / 128);   // (8, 32)
    gemm_mma<<<pgrid, 256, PRJ_SMEM>>>(query, Wq, bq, gq);
    gemm_mma<<<pgrid, 256, PRJ_SMEM>>>(key,   Wk, bk, gk);
    gemm_mma<<<pgrid, 256, PRJ_SMEM>>>(value, Wv, bv, gv);

    dim3 agrid(SS / 128, BB * HH);   // (16, 32)
    attn_mma<<<agrid, 256, ATT_SMEM>>>(gq, gk, gv, mask, go);

    gemm_mma<<<pgrid, 256, PRJ_SMEM>>>(go, Wo, bo, out);
}

// round 6
// speedup vs baseline: 2.6750x; 1.0510x over previous
#include <cuda_runtime.h>
#include <cstdint>

#define BB 2
#define SS 2048
#define EE 1024
#define HH 16
#define DHD 64
#define ME (4096 * 1024)
#define NE (1024 * 1024)

// ---------------------------------------------------------------------------
// PTX helpers (all base-sm_103 features: ldmatrix/mma.sync/cp.async)
// ---------------------------------------------------------------------------
__device__ __forceinline__ uint32_t smem_u32(const void* p) {
    uint32_t a;
    asm("{ .reg .u64 t; cvta.to.shared.u64 t, %1; cvt.u32.u64 %0, t; }" : "=r"(a) : "l"(p));
    return a;
}
__device__ __forceinline__ void ldsm4(uint32_t r[4], uint32_t a) {
    asm volatile("ldmatrix.sync.aligned.m8n8.x4.shared.b16 {%0,%1,%2,%3}, [%4];"
                 : "=r"(r[0]), "=r"(r[1]), "=r"(r[2]), "=r"(r[3]) : "r"(a));
}
__device__ __forceinline__ void ldsm4t(uint32_t r[4], uint32_t a) {
    asm volatile("ldmatrix.sync.aligned.m8n8.x4.trans.shared.b16 {%0,%1,%2,%3}, [%4];"
                 : "=r"(r[0]), "=r"(r[1]), "=r"(r[2]), "=r"(r[3]) : "r"(a));
}
__device__ __forceinline__ void mma_bf16(float d[4], const uint32_t a[4], const uint32_t b[2]) {
    asm volatile("mma.sync.aligned.m16n8k16.row.col.f32.bf16.bf16.f32 "
                 "{%0,%1,%2,%3}, {%4,%5,%6,%7}, {%8,%9}, {%0,%1,%2,%3};"
                 : "+f"(d[0]), "+f"(d[1]), "+f"(d[2]), "+f"(d[3])
                 : "r"(a[0]), "r"(a[1]), "r"(a[2]), "r"(a[3]), "r"(b[0]), "r"(b[1]));
}
// split fp32 pair -> bf16x2 hi + bf16x2 lo (x = hi + lo, exact residual)
__device__ __forceinline__ void split2(float2 v, uint32_t& hi, uint32_t& lo) {
    asm("cvt.rn.bf16x2.f32 %0, %1, %2;" : "=r"(hi) : "f"(v.y), "f"(v.x));
    float h0 = __uint_as_float(hi << 16);
    float h1 = __uint_as_float(hi & 0xFFFF0000u);
    asm("cvt.rn.bf16x2.f32 %0, %1, %2;" : "=r"(lo) : "f"(v.y - h1), "f"(v.x - h0));
}
__device__ __forceinline__ void cpa16(uint32_t dst, const void* src) {
    asm volatile("cp.async.cg.shared.global [%0], [%1], 16;" :: "r"(dst), "l"(src));
}
#define CPA_COMMIT() asm volatile("cp.async.commit_group;" ::: "memory")
#define CPA_WAIT0()  asm volatile("cp.async.wait_group 0;" ::: "memory")
#define CPA_WAIT1()  asm volatile("cp.async.wait_group 1;" ::: "memory")

// ---------------------------------------------------------------------------
// Global bf16 hi/lo scratch (allocation-free)
// ---------------------------------------------------------------------------
__device__ uint16_t g_ih[3 * ME], g_il[3 * ME];   // split inputs q,k,v
__device__ uint16_t g_wh[4 * NE], g_wl[4 * NE];   // split weights q,k,v,o
__device__ uint16_t g_ph[3 * ME], g_pl[3 * ME];   // projected Q,K,V (hi/lo)
__device__ uint16_t g_oh[ME],     g_ol[ME];       // attention output (hi/lo)

// ---------------------------------------------------------------------------
// Prep: fp32 -> bf16 hi/lo
// ---------------------------------------------------------------------------
__global__ void split_in(const float* s0, const float* s1, const float* s2,
                         uint16_t* dh, uint16_t* dl)
{
    const float* src = (blockIdx.y == 0) ? s0 : (blockIdx.y == 1 ? s1 : s2);
    const float2* sp = (const float2*)src;
    uint32_t* hp = (uint32_t*)(dh + (size_t)blockIdx.y * ME);
    uint32_t* lp = (uint32_t*)(dl + (size_t)blockIdx.y * ME);
    const int n = ME / 2;
    for (int i = blockIdx.x * blockDim.x + threadIdx.x; i < n; i += gridDim.x * blockDim.x) {
        uint32_t h, l;
        split2(sp[i], h, l);
        hp[i] = h; lp[i] = l;
    }
}
__global__ void split_w(const float* s0, const float* s1, const float* s2, const float* s3,
                        uint16_t* dh, uint16_t* dl)
{
    const float* srcs[4] = {s0, s1, s2, s3};
    const float2* sp = (const float2*)srcs[blockIdx.y];
    uint32_t* hp = (uint32_t*)(dh + (size_t)blockIdx.y * NE);
    uint32_t* lp = (uint32_t*)(dl + (size_t)blockIdx.y * NE);
    const int n = NE / 2;
    for (int i = blockIdx.x * blockDim.x + threadIdx.x; i < n; i += gridDim.x * blockDim.x) {
        uint32_t h, l;
        split2(sp[i], h, l);
        hp[i] = h; lp[i] = l;
    }
}

// ---------------------------------------------------------------------------
// Projection GEMM (bf16 hi/lo in): C = A*W^T + bias.
// Tile 128x128, BK=64, 256 thr, occ 2. mode 0: fp32 out; mode 1: hi/lo out.
// ---------------------------------------------------------------------------
#define GP 72
#define GPB 144
#define O_AHI 0
#define O_ALO 18432
#define O_BHI 36864
#define O_BLO 55296
#define PRJ_SMEM 73728

__global__ __launch_bounds__(256, 2)
void gemm_bf(const uint16_t* __restrict__ Ah, const uint16_t* __restrict__ Al,
             const uint16_t* __restrict__ Wh, const uint16_t* __restrict__ Wl,
             const float* __restrict__ bias, int mode,
             float* __restrict__ Cf, uint16_t* __restrict__ Ch, uint16_t* __restrict__ Cl)
{
    extern __shared__ char sm[];
    const uint32_t smb = smem_u32(sm);
    const int tid = threadIdx.x;
    const int bm = blockIdx.y * 128, bn = blockIdx.x * 128;
    const int w = tid >> 5, lane = tid & 31;
    const int m0 = (w & 1) * 64, n0 = (w >> 1) * 32;
    const int r8 = lane & 7, quad = lane >> 3;
    const int arow = (quad & 1) * 8 + r8, acol = (quad >> 1) * 8;
    const int brow = (quad >> 1) * 8 + r8, bcol = (quad & 1) * 8;

    float acc[4][4][4];
#pragma unroll
    for (int i = 0; i < 4; i++)
#pragma unroll
        for (int j = 0; j < 4; j++)
#pragma unroll
            for (int k = 0; k < 4; k++) acc[i][j][k] = 0.0f;

    for (int s = 0; s < 16; s++) {
        const int kk0 = s << 6;
        __syncthreads();
#pragma unroll
        for (int it = 0; it < 16; it++) {
            int idx = tid + it * 256;
            int a = idx >> 10, c = idx & 1023, row = c >> 3, cc = c & 7;
            const uint16_t* src;
            if (a == 0)      src = Ah + (size_t)(bm + row) * EE + kk0;
            else if (a == 1) src = Al + (size_t)(bm + row) * EE + kk0;
            else if (a == 2) src = Wh + (size_t)(bn + row) * EE + kk0;
            else             src = Wl + (size_t)(bn + row) * EE + kk0;
            cpa16(smb + a * 18432 + row * GPB + cc * 16, src + cc * 8);
        }
        CPA_COMMIT();
        CPA_WAIT0();
        __syncthreads();

#pragma unroll
        for (int kf = 0; kf < 4; kf++) {
            uint32_t bh[4][2], bl[4][2], t[4];
#pragma unroll
            for (int np = 0; np < 2; np++) {
                uint32_t boff = (uint32_t)((n0 + np * 16 + brow) * GP + kf * 16 + bcol) * 2;
                ldsm4(t, smb + O_BHI + boff);
                bh[np * 2][0] = t[0]; bh[np * 2][1] = t[1];
                bh[np * 2 + 1][0] = t[2]; bh[np * 2 + 1][1] = t[3];
                ldsm4(t, smb + O_BLO + boff);
                bl[np * 2][0] = t[0]; bl[np * 2][1] = t[1];
                bl[np * 2 + 1][0] = t[2]; bl[np * 2 + 1][1] = t[3];
            }
#pragma unroll
            for (int mf = 0; mf < 4; mf++) {
                uint32_t ah[4], al[4];
                uint32_t aoff = (uint32_t)((m0 + mf * 16 + arow) * GP + kf * 16 + acol) * 2;
                ldsm4(ah, smb + O_AHI + aoff);
                ldsm4(al, smb + O_ALO + aoff);
#pragma unroll
                for (int nf = 0; nf < 4; nf++) {
                    mma_bf16(acc[mf][nf], ah, bh[nf]);
                    mma_bf16(acc[mf][nf], ah, bl[nf]);
                    mma_bf16(acc[mf][nf], al, bh[nf]);
                }
            }
        }
    }

    const int g2 = lane >> 2, t2 = (lane & 3) * 2;
#pragma unroll
    for (int mf = 0; mf < 4; mf++)
#pragma unroll
        for (int nf = 0; nf < 4; nf++) {
            int row0 = bm + m0 + mf * 16 + g2;
            int col = bn + n0 + nf * 8 + t2;
            float b0 = bias[col], b1 = bias[col + 1];
            float v0 = acc[mf][nf][0] + b0, v1 = acc[mf][nf][1] + b1;
            float v2 = acc[mf][nf][2] + b0, v3 = acc[mf][nf][3] + b1;
            if (mode == 0) {
                *(float2*)(Cf + (size_t)row0 * EE + col) = make_float2(v0, v1);
                *(float2*)(Cf + (size_t)(row0 + 8) * EE + col) = make_float2(v2, v3);
            } else {
                uint32_t hi, lo;
                size_t off = (size_t)row0 * EE + col;
                split2(make_float2(v0, v1), hi, lo);
                *(uint32_t*)(Ch + off) = hi;
                *(uint32_t*)(Cl + off) = lo;
                split2(make_float2(v2, v3), hi, lo);
                off += (size_t)8 * EE;
                *(uint32_t*)(Ch + off) = hi;
                *(uint32_t*)(Cl + off) = lo;
            }
        }
}

// ---------------------------------------------------------------------------
// Fused attention (bf16 hi/lo in, hi/lo out). NO softmax.
// q-tile 128; K/V streamed in 64-row half-tiles, double-buffered cp.async.
// smem: QH/QL [128][72]; K,V stages [64][72] hi+lo x2; SH/SL [128][72].
// ---------------------------------------------------------------------------
#define AQH 0
#define AQL 18432
#define AKB(st) (36864 + (st) * 18432)
#define AVB(st) (73728 + (st) * 18432)
#define ASH 110592
#define ASL 129024
#define ATT_SMEM 147456

__device__ __forceinline__ void attn_issue_kv(
    uint32_t smb, int tid, int st, size_t kb,
    const uint16_t* kh, const uint16_t* kl,
    const uint16_t* vh, const uint16_t* vl)
{
#pragma unroll
    for (int it = 0; it < 8; it++) {
        int idx = tid + it * 256;
        int a = idx >> 9;                  // 0 KH, 1 KL, 2 VH, 3 VL
        int c = idx & 511, row = c >> 3, cc = c & 7;
        const uint16_t* src =
            (a == 0 ? kh : a == 1 ? kl : a == 2 ? vh : vl) + kb + (size_t)row * EE + cc * 8;
        uint32_t dst = smb + (a < 2 ? AKB(st) : AVB(st)) + (a & 1) * 9216 + row * GPB + cc * 16;
        cpa16(dst, src);
    }
}

__global__ __launch_bounds__(256, 1)
void attn_bf(const uint16_t* __restrict__ qh, const uint16_t* __restrict__ ql,
             const uint16_t* __restrict__ kh, const uint16_t* __restrict__ kl,
             const uint16_t* __restrict__ vh, const uint16_t* __restrict__ vl,
             const int* __restrict__ mask,
             uint16_t* __restrict__ oh, uint16_t* __restrict__ ol)
{
    extern __shared__ char sm[];
    const uint32_t smb = smem_u32(sm);
    const int tid = threadIdx.x;
    const int q0 = blockIdx.x * 128;
    const int bh = blockIdx.y, b = bh >> 4, h = bh & 15, hoff = h * DHD;
    const int w = tid >> 5, lane = tid & 31;
    const int m0 = (w & 1) * 64, wn = w >> 1;
    const int n0 = wn * 16, d0 = wn * 16;
    const int r8 = lane & 7, quad = lane >> 3;
    const int arow = (quad & 1) * 8 + r8, acol = (quad >> 1) * 8;
    const int brow = (quad >> 1) * 8 + r8, bcol = (quad & 1) * 8;
    const int g = lane >> 2, t2 = (lane & 3) * 2;

    const size_t rowbase = (size_t)b * SS;

    // prologue: Q tile + KV stage 0 (group0), KV stage 1 (group1)
    const size_t qb = (rowbase + q0) * EE + hoff;
#pragma unroll
    for (int it = 0; it < 8; it++) {
        int idx = tid + it * 256;
        int a = idx >> 10, c = idx & 1023, row = c >> 3, cc = c & 7;
        const uint16_t* src = (a ? ql : qh) + qb + (size_t)row * EE + cc * 8;
        cpa16(smb + a * 18432 + row * GPB + cc * 16, src);
    }
    attn_issue_kv(smb, tid, 0, rowbase * EE + hoff, kh, kl, vh, vl);
    CPA_COMMIT();
    attn_issue_kv(smb, tid, 1, (rowbase + 64) * EE + hoff, kh, kl, vh, vl);
    CPA_COMMIT();

    float acc2[4][2][4];
#pragma unroll
    for (int i = 0; i < 4; i++)
#pragma unroll
        for (int j = 0; j < 2; j++)
#pragma unroll
            for (int k = 0; k < 4; k++) acc2[i][j][k] = 0.0f;

    for (int ht = 0; ht < 32; ht++) {
        CPA_WAIT1();
        __syncthreads();
        const int st = ht & 1;
        const uint32_t khs = smb + AKB(st), kls = khs + 9216;
        const uint32_t vhs = smb + AVB(st), vls = vhs + 9216;

        // gemm1: S[128,64] = Q[128,64] * Khalf[64,64]^T
        float acc1[4][2][4];
#pragma unroll
        for (int i = 0; i < 4; i++)
#pragma unroll
            for (int j = 0; j < 2; j++)
#pragma unroll
                for (int k = 0; k < 4; k++) acc1[i][j][k] = 0.0f;

#pragma unroll
        for (int kf = 0; kf < 4; kf++) {
            uint32_t bhf[2][2], blf[2][2], t[4];
            uint32_t boff = (uint32_t)((n0 + brow) * GP + kf * 16 + bcol) * 2;
            ldsm4(t, khs + boff);
            bhf[0][0] = t[0]; bhf[0][1] = t[1]; bhf[1][0] = t[2]; bhf[1][1] = t[3];
            ldsm4(t, kls + boff);
            blf[0][0] = t[0]; blf[0][1] = t[1]; blf[1][0] = t[2]; blf[1][1] = t[3];
#pragma unroll
            for (int mf = 0; mf < 4; mf++) {
                uint32_t ah[4], al[4];
                uint32_t aoff = (uint32_t)((m0 + mf * 16 + arow) * GP + kf * 16 + acol) * 2;
                ldsm4(ah, smb + AQH + aoff);
                ldsm4(al, smb + AQL + aoff);
#pragma unroll
                for (int nf = 0; nf < 2; nf++) {
                    mma_bf16(acc1[mf][nf], ah, bhf[nf]);
                    mma_bf16(acc1[mf][nf], ah, blf[nf]);
                    mma_bf16(acc1[mf][nf], al, bhf[nf]);
                }
            }
        }

        // scale + mask + split-store S
        const int kg0 = ht * 64;
#pragma unroll
        for (int mf = 0; mf < 4; mf++)
#pragma unroll
            for (int nf = 0; nf < 2; nf++) {
                int rl = m0 + mf * 16 + g;
                int cl = n0 + nf * 8 + t2;
                const int* mp = mask + (rowbase + q0 + rl) * SS + kg0 + cl;
                int2 ma = *(const int2*)mp;
                int2 mb2 = *(const int2*)(mp + (size_t)8 * SS);
                float v0 = ma.x ? acc1[mf][nf][0] * 0.125f : 1e-9f;
                float v1 = ma.y ? acc1[mf][nf][1] * 0.125f : 1e-9f;
                float v2 = mb2.x ? acc1[mf][nf][2] * 0.125f : 1e-9f;
                float v3 = mb2.y ? acc1[mf][nf][3] * 0.125f : 1e-9f;
                uint32_t hi, lo;
                split2(make_float2(v0, v1), hi, lo);
                *(uint32_t*)(sm + ASH + rl * GPB + cl * 2) = hi;
                *(uint32_t*)(sm + ASL + rl * GPB + cl * 2) = lo;
                split2(make_float2(v2, v3), hi, lo);
                *(uint32_t*)(sm + ASH + (rl + 8) * GPB + cl * 2) = hi;
                *(uint32_t*)(sm + ASL + (rl + 8) * GPB + cl * 2) = lo;
            }
        __syncthreads();

        // gemm2: O[128,64] += S[128,64] * Vhalf[64,64]
#pragma unroll
        for (int kf = 0; kf < 4; kf++) {
            uint32_t bhf[2][2], blf[2][2], t[4];
            uint32_t voff = (uint32_t)((kf * 16 + (quad & 1) * 8 + r8) * GP +
                                       d0 + (quad >> 1) * 8) * 2;
            ldsm4t(t, vhs + voff);
            bhf[0][0] = t[0]; bhf[0][1] = t[1]; bhf[1][0] = t[2]; bhf[1][1] = t[3];
            ldsm4t(t, vls + voff);
            blf[0][0] = t[0]; blf[0][1] = t[1]; blf[1][0] = t[2]; blf[1][1] = t[3];
#pragma unroll
            for (int mf = 0; mf < 4; mf++) {
                uint32_t sh[4], sl[4];
                uint32_t soff = (uint32_t)((m0 + mf * 16 + arow) * GP + kf * 16 + acol) * 2;
                ldsm4(sh, smb + ASH + soff);
                ldsm4(sl, smb + ASL + soff);
#pragma unroll
                for (int nf = 0; nf < 2; nf++) {
                    mma_bf16(acc2[mf][nf], sh, bhf[nf]);
                    mma_bf16(acc2[mf][nf], sh, blf[nf]);
                    mma_bf16(acc2[mf][nf], sl, bhf[nf]);
                }
            }
        }
        __syncthreads();
        if (ht + 2 < 32)
            attn_issue_kv(smb, tid, st, (rowbase + (ht + 2) * 64) * EE + hoff, kh, kl, vh, vl);
        CPA_COMMIT();   // unconditional: keeps group accounting uniform
    }

    // epilogue: split O to hi/lo bf16
#pragma unroll
    for (int mf = 0; mf < 4; mf++)
#pragma unroll
        for (int nf = 0; nf < 2; nf++) {
            int row = q0 + m0 + mf * 16 + g;
            int col = hoff + d0 + nf * 8 + t2;
            uint32_t hi, lo;
            size_t off = (rowbase + row) * EE + col;
            split2(make_float2(acc2[mf][nf][0], acc2[mf][nf][1]), hi, lo);
            *(uint32_t*)(oh + off) = hi;
            *(uint32_t*)(ol + off) = lo;
            split2(make_float2(acc2[mf][nf][2], acc2[mf][nf][3]), hi, lo);
            off += (size_t)8 * EE;
            *(uint32_t*)(oh + off) = hi;
            *(uint32_t*)(ol + off) = lo;
        }
}

// ---------------------------------------------------------------------------
extern "C" void kernel_launch(void* const* d_in, const int* in_sizes, int n_in,
                              void* d_out, int out_size)
{
    const float* query = (const float*)d_in[0];
    const float* key   = (const float*)d_in[1];
    const float* value = (const float*)d_in[2];
    const int*   mask  = (const int*)  d_in[3];
    const float* Wq    = (const float*)d_in[4];
    const float* bq    = (const float*)d_in[5];
    const float* Wk    = (const float*)d_in[6];
    const float* bk    = (const float*)d_in[7];
    const float* Wv    = (const float*)d_in[8];
    const float* bv    = (const float*)d_in[9];
    const float* Wo    = (const float*)d_in[10];
    const float* bo    = (const float*)d_in[11];
    float* out = (float*)d_out;

    uint16_t *ih, *il, *wh, *wl, *ph, *pl, *oh, *ol;
    cudaGetSymbolAddress((void**)&ih, g_ih);
    cudaGetSymbolAddress((void**)&il, g_il);
    cudaGetSymbolAddress((void**)&wh, g_wh);
    cudaGetSymbolAddress((void**)&wl, g_wl);
    cudaGetSymbolAddress((void**)&ph, g_ph);
    cudaGetSymbolAddress((void**)&pl, g_pl);
    cudaGetSymbolAddress((void**)&oh, g_oh);
    cudaGetSymbolAddress((void**)&ol, g_ol);

    cudaFuncSetAttribute(gemm_bf, cudaFuncAttributeMaxDynamicSharedMemorySize, PRJ_SMEM);
    cudaFuncSetAttribute(attn_bf, cudaFuncAttributeMaxDynamicSharedMemorySize, ATT_SMEM);

    split_in<<<dim3(512, 3), 256>>>(query, key, value, ih, il);
    split_w<<<dim3(256, 4), 256>>>(Wq, Wk, Wv, Wo, wh, wl);

    dim3 pgrid(EE / 128, (BB * SS) / 128);   // (8, 32)
    gemm_bf<<<pgrid, 256, PRJ_SMEM>>>(ih,          il,          wh,          wl,          bq, 1, nullptr, ph,          pl);
    gemm_bf<<<pgrid, 256, PRJ_SMEM>>>(ih + ME,     il + ME,     wh + NE,     wl + NE,     bk, 1, nullptr, ph + ME,     pl + ME);
    gemm_bf<<<pgrid, 256, PRJ_SMEM>>>(ih + 2 * ME, il + 2 * ME, wh + 2 * NE, wl + 2 * NE, bv, 1, nullptr, ph + 2 * ME, pl + 2 * ME);

    dim3 agrid(SS / 128, BB * HH);   // (16, 32)
    attn_bf<<<agrid, 256, ATT_SMEM>>>(ph, pl, ph + ME, pl + ME, ph + 2 * ME, pl + 2 * ME,
                                      mask, oh, ol);

    gemm_bf<<<pgrid, 256, PRJ_SMEM>>>(oh, ol, wh + 3 * NE, wl + 3 * NE, bo, 0, out, nullptr, nullptr);
}